// round 9
// baseline (speedup 1.0000x reference)
#include <cuda_runtime.h>
#include <cuda_bf16.h>

// Problem constants
#define T_STEPS 1024
#define NK      16
#define HID     20
#define GATES   80
#define CELLS   1024
#define WARPS_PER_CTA 8
#define NTHREADS (WARPS_PER_CTA * 32)   // 256
#define CTAS    (CELLS / WARPS_PER_CTA) // 128
#define ROWF    32                      // padded hbuf row (128B)
#define XSTRIDE 48                      // NK*3 floats per time step

__device__ float g_y[CELLS + 1];
__device__ int   g_done;

typedef unsigned long long ull;

// ---------- packed f32x2 + MUFU helpers ----------
__device__ __forceinline__ ull pk2(float lo, float hi) {
    ull r;
    asm("mov.b64 %0, {%1, %2};" : "=l"(r) : "f"(lo), "f"(hi));
    return r;
}
__device__ __forceinline__ void upk2(ull v, float& lo, float& hi) {
    asm("mov.b64 {%0, %1}, %2;" : "=f"(lo), "=f"(hi) : "l"(v));
}
__device__ __forceinline__ void fma2(ull& d, ull a, ull b) {
    asm("fma.rn.f32x2 %0, %1, %2, %0;" : "+l"(d) : "l"(a), "l"(b));
}
__device__ __forceinline__ ull add2(ull a, ull b) {
    ull r;
    asm("add.rn.f32x2 %0, %1, %2;" : "=l"(r) : "l"(a), "l"(b));
    return r;
}
__device__ __forceinline__ float ex2f(float x) {
    float r; asm("ex2.approx.f32 %0, %1;" : "=f"(r) : "f"(x)); return r;
}
__device__ __forceinline__ float rcpf(float x) {
    float r; asm("rcp.approx.f32 %0, %1;" : "=f"(r) : "f"(x)); return r;
}
// HW tanh (MUFU.TANH)
__device__ __forceinline__ float tanha(float x) {
    float r; asm("tanh.approx.f32 %0, %1;" : "=f"(r) : "f"(x)); return r;
}
// precise tanh for the head (off the hot loop)
__device__ __forceinline__ float tanhx(float x) {
    float e = ex2f(2.8853900817779268f * x);
    return fmaf(-2.0f, rcpf(e + 1.0f), 1.0f);
}

// ---------- fused kernel: scan + head + (last CTA) softmax ----------
__global__ void __launch_bounds__(NTHREADS, 1)
lstm_fused(const float* __restrict__ inp,   // [B,T,K,I]
           const float* __restrict__ w,     // [K*B+1]
           const float* __restrict__ W_ih,  // [K,4H,I]
           const float* __restrict__ W_hh,  // [K,4H,H]
           const float* __restrict__ b_ih,  // [K,4H]
           const float* __restrict__ b_hh,  // [K,4H]
           const float* __restrict__ conv_w,// [H+1]
           const float* __restrict__ conv_b,// scalar
           float* __restrict__ out)         // [1025]
{
    __shared__ __align__(16) float hbuf[WARPS_PER_CTA][ROWF];
    __shared__ float red[32];
    __shared__ int   s_last;

    const int tid  = threadIdx.x;
    const int wid  = tid >> 5;
    const int lane = tid & 31;
    const int cell = blockIdx.x * WARPS_PER_CTA + wid;   // = k*64 + b
    const int k    = cell >> 6;
    const int b    = cell & 63;
    const int ju   = (lane < HID) ? lane : (HID - 1);    // lanes 20..31 duplicate unit 19

    // ---- preload weights; fold sigmoid's 0.5 pre-scale into gates i,f,o (g unscaled) ----
    ull   whh[4][10];
    float wx[4][3], bs[4];
#pragma unroll
    for (int g = 0; g < 4; ++g) {
        const float sc  = (g == 2) ? 1.0f : 0.5f;
        const int   row = k * GATES + g * HID + ju;
        const float* wr = W_hh + (size_t)row * HID;
#pragma unroll
        for (int m = 0; m < 10; ++m) {
            float2 v = *reinterpret_cast<const float2*>(wr + 2 * m);
            whh[g][m] = pk2(v.x * sc, v.y * sc);
        }
        wx[g][0] = W_ih[(size_t)row * 3 + 0] * sc;
        wx[g][1] = W_ih[(size_t)row * 3 + 1] * sc;
        wx[g][2] = W_ih[(size_t)row * 3 + 2] * sc;
        bs[g]    = (b_ih[row] + b_hh[row]) * sc;
    }

    // this warp's h row viewed as 5 × 16B (pairs (h0,h1|h2,h3), ...)
    const ulonglong2* hrow = reinterpret_cast<const ulonglong2*>(&hbuf[wid][0]);

    // ---- init state ----
    if (lane < HID) hbuf[wid][lane] = 0.0f;
    float c = 0.0f, h = 0.0f;

    const float* ip = inp + (size_t)b * (T_STEPS * XSTRIDE) + k * 3;

    // ---- 4-slot raw-x register ring (LDG→use distance = 4 steps) ----
    float A0 = ip[1 * XSTRIDE + 0], A1 = ip[1 * XSTRIDE + 1], A2 = ip[1 * XSTRIDE + 2];
    float B0 = ip[2 * XSTRIDE + 0], B1 = ip[2 * XSTRIDE + 1], B2 = ip[2 * XSTRIDE + 2];
    float C0 = ip[3 * XSTRIDE + 0], C1 = ip[3 * XSTRIDE + 1], C2 = ip[3 * XSTRIDE + 2];
    float D0 = ip[4 * XSTRIDE + 0], D1 = ip[4 * XSTRIDE + 1], D2 = ip[4 * XSTRIDE + 2];

    float ps0, ps1, ps2, ps3;   // proj(current step)
    {
        const float x0 = ip[0], x1 = ip[1], x2 = ip[2];
        ps0 = fmaf(wx[0][2], x2, fmaf(wx[0][1], x1, fmaf(wx[0][0], x0, bs[0])));
        ps1 = fmaf(wx[1][2], x2, fmaf(wx[1][1], x1, fmaf(wx[1][0], x0, bs[1])));
        ps2 = fmaf(wx[2][2], x2, fmaf(wx[2][1], x1, fmaf(wx[2][0], x0, bs[2])));
        ps3 = fmaf(wx[3][2], x2, fmaf(wx[3][1], x1, fmaf(wx[3][0], x0, bs[3])));
    }
    __syncwarp();

    // One LSTM step. Slot regs S0..S2 hold x(s+1): used for proj(s+1), then
    // reloaded with x(s+5). All 5 h-pair smem loads are plain C++ loads issued
    // BEFORE any FMA so ptxas can front-batch them (one exposed LDS latency
    // per step instead of five serialized round trips).
#define LSTM_STEP(S0, S1, S2, TRELOAD)                                          \
    do {                                                                        \
        /* batch-load all h pairs for this step (LDS.128 x5, broadcast) */      \
        const ulonglong2 v0 = hrow[0];                                          \
        const ulonglong2 v1 = hrow[1];                                          \
        const ulonglong2 v2 = hrow[2];                                          \
        const ulonglong2 v3 = hrow[3];                                          \
        const ulonglong2 v4 = hrow[4];                                          \
        /* proj(s+1) from the slot (loaded 4 steps ago — no wait) */            \
        const float n0 = fmaf(wx[0][2], S2, fmaf(wx[0][1], S1, fmaf(wx[0][0], S0, bs[0]))); \
        const float n1 = fmaf(wx[1][2], S2, fmaf(wx[1][1], S1, fmaf(wx[1][0], S0, bs[1]))); \
        const float n2 = fmaf(wx[2][2], S2, fmaf(wx[2][1], S1, fmaf(wx[2][0], S0, bs[2]))); \
        const float n3 = fmaf(wx[3][2], S2, fmaf(wx[3][1], S1, fmaf(wx[3][0], S0, bs[3]))); \
        /* reload slot with x(s+5); consumed 4 steps from now */                \
        {                                                                       \
            int tr = (TRELOAD); if (tr > T_STEPS - 1) tr = T_STEPS - 1;         \
            const float* pp = ip + (size_t)tr * XSTRIDE;                        \
            S0 = pp[0]; S1 = pp[1]; S2 = pp[2];                                 \
        }                                                                       \
        /* recurrent matvec: 2 partial chains per gate (depth 5 each) */        \
        ull a0e = pk2(ps0, 0.0f), a0o = 0ULL;                                   \
        ull a1e = pk2(ps1, 0.0f), a1o = 0ULL;                                   \
        ull a2e = pk2(ps2, 0.0f), a2o = 0ULL;                                   \
        ull a3e = pk2(ps3, 0.0f), a3o = 0ULL;                                   \
        fma2(a0e, whh[0][0], v0.x); fma2(a0o, whh[0][1], v0.y);                 \
        fma2(a1e, whh[1][0], v0.x); fma2(a1o, whh[1][1], v0.y);                 \
        fma2(a2e, whh[2][0], v0.x); fma2(a2o, whh[2][1], v0.y);                 \
        fma2(a3e, whh[3][0], v0.x); fma2(a3o, whh[3][1], v0.y);                 \
        fma2(a0e, whh[0][2], v1.x); fma2(a0o, whh[0][3], v1.y);                 \
        fma2(a1e, whh[1][2], v1.x); fma2(a1o, whh[1][3], v1.y);                 \
        fma2(a2e, whh[2][2], v1.x); fma2(a2o, whh[2][3], v1.y);                 \
        fma2(a3e, whh[3][2], v1.x); fma2(a3o, whh[3][3], v1.y);                 \
        fma2(a0e, whh[0][4], v2.x); fma2(a0o, whh[0][5], v2.y);                 \
        fma2(a1e, whh[1][4], v2.x); fma2(a1o, whh[1][5], v2.y);                 \
        fma2(a2e, whh[2][4], v2.x); fma2(a2o, whh[2][5], v2.y);                 \
        fma2(a3e, whh[3][4], v2.x); fma2(a3o, whh[3][5], v2.y);                 \
        fma2(a0e, whh[0][6], v3.x); fma2(a0o, whh[0][7], v3.y);                 \
        fma2(a1e, whh[1][6], v3.x); fma2(a1o, whh[1][7], v3.y);                 \
        fma2(a2e, whh[2][6], v3.x); fma2(a2o, whh[2][7], v3.y);                 \
        fma2(a3e, whh[3][6], v3.x); fma2(a3o, whh[3][7], v3.y);                 \
        fma2(a0e, whh[0][8], v4.x); fma2(a0o, whh[0][9], v4.y);                 \
        fma2(a1e, whh[1][8], v4.x); fma2(a1o, whh[1][9], v4.y);                 \
        fma2(a2e, whh[2][8], v4.x); fma2(a2o, whh[2][9], v4.y);                 \
        fma2(a3e, whh[3][8], v4.x); fma2(a3o, whh[3][9], v4.y);                 \
        /* c-path gates first (i,f,g), o-gate last (off the c chain) */         \
        float lo, hi, gi, gf, gg, go;                                           \
        upk2(add2(a0e, a0o), lo, hi); gi = lo + hi;                             \
        upk2(add2(a1e, a1o), lo, hi); gf = lo + hi;                             \
        upk2(add2(a2e, a2o), lo, hi); gg = lo + hi;                             \
        const float si = fmaf(0.5f, tanha(gi), 0.5f);                           \
        const float sf = fmaf(0.5f, tanha(gf), 0.5f);                           \
        const float tg = tanha(gg);                                             \
        upk2(add2(a3e, a3o), lo, hi); go = lo + hi;                             \
        const float so = fmaf(0.5f, tanha(go), 0.5f);                           \
        c = fmaf(sf, c, si * tg);                                               \
        h = so * tanha(c);                                                      \
        if (lane < HID) hbuf[wid][lane] = h;                                    \
        __syncwarp();                                                           \
        ps0 = n0; ps1 = n1; ps2 = n2; ps3 = n3;                                 \
    } while (0)

#pragma unroll 1
    for (int t = 0; t < T_STEPS; t += 4) {
        LSTM_STEP(A0, A1, A2, t + 5);
        LSTM_STEP(B0, B1, B2, t + 6);
        LSTM_STEP(C0, C1, C2, t + 7);
        LSTM_STEP(D0, D1, D2, t + 8);
    }
#undef LSTM_STEP

    // ---- head: y = tanh( dot(h, conv_w[0:20]) + w[1+cell]*conv_w[20] + conv_b ) ----
    float contrib = (lane < HID) ? h * conv_w[lane] : 0.0f;
#pragma unroll
    for (int o = 16; o; o >>= 1)
        contrib += __shfl_xor_sync(0xffffffffu, contrib, o);
    if (lane == 0) {
        float yv = tanhx(contrib + w[1 + cell] * conv_w[HID] + conv_b[0]);
        g_y[1 + cell] = yv;
        if (cell == 0) g_y[0] = 1.0f;   // prepended cash constant
    }

    // ---- completion protocol (threadFenceReduction pattern) ----
    __threadfence();
    __syncthreads();
    if (tid == 0) {
        int prev = atomicAdd(&g_done, 1);
        s_last = (prev == CTAS - 1);
    }
    __syncthreads();
    if (!s_last) return;
    if (tid == 0) g_done = 0;   // reset for next graph replay

    // ---- last CTA: softmax over y[0..1024] (256 threads, 4 values each + 1 extra) ----
    float v[4];
#pragma unroll
    for (int q = 0; q < 4; ++q) v[q] = __ldcg(&g_y[tid + 256 * q]);
    float vx = (tid == 0) ? __ldcg(&g_y[CELLS]) : -3.0e38f;

    // block max
    float m = fmaxf(fmaxf(fmaxf(v[0], v[1]), fmaxf(v[2], v[3])), vx);
#pragma unroll
    for (int o = 16; o; o >>= 1) m = fmaxf(m, __shfl_xor_sync(0xffffffffu, m, o));
    if (lane == 0) red[wid] = m;
    __syncthreads();
    if (wid == 0) {
        float mm = (lane < WARPS_PER_CTA) ? red[lane] : -3.0e38f;
#pragma unroll
        for (int o = 4; o; o >>= 1) mm = fmaxf(mm, __shfl_xor_sync(0xffffffffu, mm, o));
        if (lane == 0) red[0] = mm;
    }
    __syncthreads();
    const float M = red[0];
    __syncthreads();

    float e[4];
#pragma unroll
    for (int q = 0; q < 4; ++q) e[q] = ex2f((v[q] - M) * 1.4426950408889634f);
    float ex = (tid == 0) ? ex2f((vx - M) * 1.4426950408889634f) : 0.0f;

    // block sum
    float s = e[0] + e[1] + e[2] + e[3] + ex;
#pragma unroll
    for (int o = 16; o; o >>= 1) s += __shfl_xor_sync(0xffffffffu, s, o);
    if (lane == 0) red[wid] = s;
    __syncthreads();
    if (wid == 0) {
        float ss = (lane < WARPS_PER_CTA) ? red[lane] : 0.0f;
#pragma unroll
        for (int o = 4; o; o >>= 1) ss += __shfl_xor_sync(0xffffffffu, ss, o);
        if (lane == 0) red[0] = ss;
    }
    __syncthreads();
    const float inv = rcpf(red[0]);

#pragma unroll
    for (int q = 0; q < 4; ++q) out[tid + 256 * q] = e[q] * inv;
    if (tid == 0) out[CELLS] = ex * inv;
}

extern "C" void kernel_launch(void* const* d_in, const int* in_sizes, int n_in,
                              void* d_out, int out_size)
{
    const float* inp    = (const float*)d_in[0];
    const float* w      = (const float*)d_in[1];
    const float* W_ih   = (const float*)d_in[2];
    const float* W_hh   = (const float*)d_in[3];
    const float* b_ih   = (const float*)d_in[4];
    const float* b_hh   = (const float*)d_in[5];
    const float* conv_w = (const float*)d_in[6];
    const float* conv_b = (const float*)d_in[7];
    float* out = (float*)d_out;

    lstm_fused<<<CTAS, NTHREADS>>>(inp, w, W_ih, W_hh, b_ih, b_hh,
                                   conv_w, conv_b, out);
}

// round 10
// speedup vs baseline: 1.2620x; 1.2620x over previous
#include <cuda_runtime.h>
#include <cuda_bf16.h>

// Problem constants
#define T_STEPS 1024
#define NK      16
#define HID     20
#define GATES   80
#define CELLS   1024
#define WARPS_PER_CTA 8
#define NTHREADS (WARPS_PER_CTA * 32)   // 256
#define CTAS    (CELLS / WARPS_PER_CTA) // 128
#define XSTRIDE 48                      // NK*3 floats per time step

__device__ float g_y[CELLS + 1];
__device__ int   g_done;

typedef unsigned long long ull;

// ---------- packed f32x2 + MUFU helpers ----------
__device__ __forceinline__ ull pk2(float lo, float hi) {
    ull r;
    asm("mov.b64 %0, {%1, %2};" : "=l"(r) : "f"(lo), "f"(hi));
    return r;
}
__device__ __forceinline__ void upk2(ull v, float& lo, float& hi) {
    asm("mov.b64 {%0, %1}, %2;" : "=f"(lo), "=f"(hi) : "l"(v));
}
__device__ __forceinline__ void fma2(ull& d, ull a, ull b) {
    asm("fma.rn.f32x2 %0, %1, %2, %0;" : "+l"(d) : "l"(a), "l"(b));
}
__device__ __forceinline__ float ex2f(float x) {
    float r; asm("ex2.approx.f32 %0, %1;" : "=f"(r) : "f"(x)); return r;
}
__device__ __forceinline__ float rcpf(float x) {
    float r; asm("rcp.approx.f32 %0, %1;" : "=f"(r) : "f"(x)); return r;
}
// HW tanh (MUFU.TANH)
__device__ __forceinline__ float tanha(float x) {
    float r; asm("tanh.approx.f32 %0, %1;" : "=f"(r) : "f"(x)); return r;
}
// precise tanh for the head (off the hot loop)
__device__ __forceinline__ float tanhx(float x) {
    float e = ex2f(2.8853900817779268f * x);
    return fmaf(-2.0f, rcpf(e + 1.0f), 1.0f);
}

// ---------- fused kernel: scan + head + (last CTA) softmax ----------
__global__ void __launch_bounds__(NTHREADS, 1)
lstm_fused(const float* __restrict__ inp,   // [B,T,K,I]
           const float* __restrict__ w,     // [K*B+1]
           const float* __restrict__ W_ih,  // [K,4H,I]
           const float* __restrict__ W_hh,  // [K,4H,H]
           const float* __restrict__ b_ih,  // [K,4H]
           const float* __restrict__ b_hh,  // [K,4H]
           const float* __restrict__ conv_w,// [H+1]
           const float* __restrict__ conv_b,// scalar
           float* __restrict__ out)         // [1025]
{
    // h row: half0 at [0..9], half1 at [16..25] (both 16B-aligned + 8B tail)
    __shared__ __align__(16) float hbuf[WARPS_PER_CTA][32];
    // half-row partial sums: logical index 2*row+half == 32*m + lane
    __shared__ __align__(16) float gbuf[WARPS_PER_CTA][160];
    __shared__ float red[32];
    __shared__ int   s_last;

    const int tid  = threadIdx.x;
    const int wid  = tid >> 5;
    const int lane = tid & 31;
    const int cell = blockIdx.x * WARPS_PER_CTA + wid;   // = k*64 + b
    const int k    = cell >> 6;
    const int b    = cell & 63;
    const int pr   = lane >> 1;          // 0..15 : row group
    const int hf   = lane & 1;           // 0/1   : which half of h
    const int jj   = (lane < HID) ? lane : (HID - 1);   // gather unit (clamped)

    // ---- recurrent weights: lane L, slot m <-> half hf of row 16m+pr ----
    // 0.5 sigmoid pre-scale folded into rows of gates i,f,o (gate = row/20).
    ull wsp[5][5];
#pragma unroll
    for (int m = 0; m < 5; ++m) {
        const int row = 16 * m + pr;
        const float sc = (row / 20 == 2) ? 1.0f : 0.5f;
        const float* wr = W_hh + ((size_t)(k * GATES + row)) * HID + 10 * hf;
#pragma unroll
        for (int i = 0; i < 5; ++i)
            wsp[m][i] = pk2(wr[2 * i] * sc, wr[2 * i + 1] * sc);
    }

    // ---- gather-lane weights: unit jj -> rows jj, 20+jj, 40+jj, 60+jj ----
    ull wiA[3], wiB[3], bA, bB;
    {
        const int r0 = k * GATES + jj;        // gate i (x0.5)
        const int r1 = r0 + 20;               // gate f (x0.5)
        const int r2 = r0 + 40;               // gate g (x1.0)
        const int r3 = r0 + 60;               // gate o (x0.5)
#pragma unroll
        for (int x = 0; x < 3; ++x) {
            wiA[x] = pk2(W_ih[(size_t)r0 * 3 + x] * 0.5f, W_ih[(size_t)r1 * 3 + x] * 0.5f);
            wiB[x] = pk2(W_ih[(size_t)r2 * 3 + x],        W_ih[(size_t)r3 * 3 + x] * 0.5f);
        }
        bA = pk2((b_ih[r0] + b_hh[r0]) * 0.5f, (b_ih[r1] + b_hh[r1]) * 0.5f);
        bB = pk2((b_ih[r2] + b_hh[r2]),        (b_ih[r3] + b_hh[r3]) * 0.5f);
    }

    // smem pointers
    const char*   hhalf  = (const char*)&hbuf[wid][0] + hf * 64;  // my 40B half
    float*        hstore = &hbuf[wid][jj + ((jj >= 10) ? 6 : 0)]; // padded slot
    float*        gb     = &gbuf[wid][0];
    const float2* gp     = (const float2*)&gbuf[wid][0];          // gp[row] = (half0,half1)

    // ---- init state ----
    hbuf[wid][lane] = 0.0f;     // zero both halves incl. padding
    float c = 0.0f, h = 0.0f;

    const float* ip = inp + (size_t)b * (T_STEPS * XSTRIDE) + k * 3;

    // ---- 4-slot raw-x ring: slot[t&3] holds x(t); reload x(t+4) after use ----
    float A0 = ip[0 * XSTRIDE + 0], A1 = ip[0 * XSTRIDE + 1], A2 = ip[0 * XSTRIDE + 2];
    float B0 = ip[1 * XSTRIDE + 0], B1 = ip[1 * XSTRIDE + 1], B2 = ip[1 * XSTRIDE + 2];
    float C0 = ip[2 * XSTRIDE + 0], C1 = ip[2 * XSTRIDE + 1], C2 = ip[2 * XSTRIDE + 2];
    float D0 = ip[3 * XSTRIDE + 0], D1 = ip[3 * XSTRIDE + 1], D2 = ip[3 * XSTRIDE + 2];
    __syncwarp();

#define LSTM_STEP(S0, S1, S2, TRELOAD)                                          \
    do {                                                                        \
        /* my half of h: 5 pairs via 2x LDS.128 + LDS.64 */                     \
        const ulonglong2 u0 = *(const ulonglong2*)(hhalf);                      \
        const ulonglong2 u1 = *(const ulonglong2*)(hhalf + 16);                 \
        const ull        u2 = *(const ull*)(hhalf + 32);                        \
        /* 5 half-row accumulators x depth-5 FFMA2 */                           \
        ull a0 = 0ULL, a1 = 0ULL, a2 = 0ULL, a3 = 0ULL, a4 = 0ULL;              \
        fma2(a0, wsp[0][0], u0.x); fma2(a1, wsp[1][0], u0.x);                   \
        fma2(a2, wsp[2][0], u0.x); fma2(a3, wsp[3][0], u0.x);                   \
        fma2(a4, wsp[4][0], u0.x);                                              \
        fma2(a0, wsp[0][1], u0.y); fma2(a1, wsp[1][1], u0.y);                   \
        fma2(a2, wsp[2][1], u0.y); fma2(a3, wsp[3][1], u0.y);                   \
        fma2(a4, wsp[4][1], u0.y);                                              \
        fma2(a0, wsp[0][2], u1.x); fma2(a1, wsp[1][2], u1.x);                   \
        fma2(a2, wsp[2][2], u1.x); fma2(a3, wsp[3][2], u1.x);                   \
        fma2(a4, wsp[4][2], u1.x);                                              \
        fma2(a0, wsp[0][3], u1.y); fma2(a1, wsp[1][3], u1.y);                   \
        fma2(a2, wsp[2][3], u1.y); fma2(a3, wsp[3][3], u1.y);                   \
        fma2(a4, wsp[4][3], u1.y);                                              \
        fma2(a0, wsp[0][4], u2);   fma2(a1, wsp[1][4], u2);                     \
        fma2(a2, wsp[2][4], u2);   fma2(a3, wsp[3][4], u2);                     \
        fma2(a4, wsp[4][4], u2);                                                \
        /* horizontal lo+hi -> conflict-free scalar stores */                   \
        float lo, hi;                                                           \
        upk2(a0, lo, hi); gb[lane]       = lo + hi;                             \
        upk2(a1, lo, hi); gb[32 + lane]  = lo + hi;                             \
        upk2(a2, lo, hi); gb[64 + lane]  = lo + hi;                             \
        upk2(a3, lo, hi); gb[96 + lane]  = lo + hi;                             \
        upk2(a4, lo, hi); gb[128 + lane] = lo + hi;                             \
        __syncwarp();                                                           \
        /* input projection (packed over gate pairs) in the gather shadow */    \
        const ull xq0 = pk2(S0, S0), xq1 = pk2(S1, S1), xq2 = pk2(S2, S2);      \
        ull pA = bA, pB = bB;                                                   \
        fma2(pA, wiA[0], xq0); fma2(pA, wiA[1], xq1); fma2(pA, wiA[2], xq2);    \
        fma2(pB, wiB[0], xq0); fma2(pB, wiB[1], xq1); fma2(pB, wiB[2], xq2);    \
        /* reload ring slot with x(t+4) */                                      \
        {                                                                       \
            int tr = (TRELOAD); if (tr > T_STEPS - 1) tr = T_STEPS - 1;         \
            const float* pp = ip + (size_t)tr * XSTRIDE;                        \
            S0 = pp[0]; S1 = pp[1]; S2 = pp[2];                                 \
        }                                                                       \
        /* gather my unit's 4 gates: (half0, half1) per row */                  \
        const float2 r0 = gp[jj];                                               \
        const float2 r1 = gp[20 + jj];                                          \
        const float2 r2 = gp[40 + jj];                                          \
        const float2 r3 = gp[60 + jj];                                          \
        float pi_, pf_, pg_, po_;                                               \
        upk2(pA, pi_, pf_);                                                     \
        upk2(pB, pg_, po_);                                                     \
        const float gi = r0.x + r0.y + pi_;                                     \
        const float gf = r1.x + r1.y + pf_;                                     \
        const float gg = r2.x + r2.y + pg_;                                     \
        const float si = fmaf(0.5f, tanha(gi), 0.5f);                           \
        const float sf = fmaf(0.5f, tanha(gf), 0.5f);                           \
        const float tg = tanha(gg);                                             \
        const float go = r3.x + r3.y + po_;                                     \
        const float so = fmaf(0.5f, tanha(go), 0.5f);                           \
        c = fmaf(sf, c, si * tg);                                               \
        h = so * tanha(c);                                                      \
        if (lane < HID) *hstore = h;                                            \
        __syncwarp();                                                           \
    } while (0)

#pragma unroll 1
    for (int t = 0; t < T_STEPS; t += 4) {
        LSTM_STEP(A0, A1, A2, t + 4);
        LSTM_STEP(B0, B1, B2, t + 5);
        LSTM_STEP(C0, C1, C2, t + 6);
        LSTM_STEP(D0, D1, D2, t + 7);
    }
#undef LSTM_STEP

    // ---- head: y = tanh( dot(h, conv_w[0:20]) + w[1+cell]*conv_w[20] + conv_b ) ----
    float contrib = (lane < HID) ? h * conv_w[lane] : 0.0f;
#pragma unroll
    for (int o = 16; o; o >>= 1)
        contrib += __shfl_xor_sync(0xffffffffu, contrib, o);
    if (lane == 0) {
        float yv = tanhx(contrib + w[1 + cell] * conv_w[HID] + conv_b[0]);
        g_y[1 + cell] = yv;
        if (cell == 0) g_y[0] = 1.0f;   // prepended cash constant
    }

    // ---- completion protocol (threadFenceReduction pattern) ----
    __threadfence();
    __syncthreads();
    if (tid == 0) {
        int prev = atomicAdd(&g_done, 1);
        s_last = (prev == CTAS - 1);
    }
    __syncthreads();
    if (!s_last) return;
    if (tid == 0) g_done = 0;   // reset for next graph replay

    // ---- last CTA: softmax over y[0..1024] (256 threads, 4 values each + 1 extra) ----
    float v[4];
#pragma unroll
    for (int q = 0; q < 4; ++q) v[q] = __ldcg(&g_y[tid + 256 * q]);
    float vx = (tid == 0) ? __ldcg(&g_y[CELLS]) : -3.0e38f;

    // block max
    float m = fmaxf(fmaxf(fmaxf(v[0], v[1]), fmaxf(v[2], v[3])), vx);
#pragma unroll
    for (int o = 16; o; o >>= 1) m = fmaxf(m, __shfl_xor_sync(0xffffffffu, m, o));
    if (lane == 0) red[wid] = m;
    __syncthreads();
    if (wid == 0) {
        float mm = (lane < WARPS_PER_CTA) ? red[lane] : -3.0e38f;
#pragma unroll
        for (int o = 4; o; o >>= 1) mm = fmaxf(mm, __shfl_xor_sync(0xffffffffu, mm, o));
        if (lane == 0) red[0] = mm;
    }
    __syncthreads();
    const float M = red[0];
    __syncthreads();

    float e[4];
#pragma unroll
    for (int q = 0; q < 4; ++q) e[q] = ex2f((v[q] - M) * 1.4426950408889634f);
    float ex = (tid == 0) ? ex2f((vx - M) * 1.4426950408889634f) : 0.0f;

    // block sum
    float s = e[0] + e[1] + e[2] + e[3] + ex;
#pragma unroll
    for (int o = 16; o; o >>= 1) s += __shfl_xor_sync(0xffffffffu, s, o);
    if (lane == 0) red[wid] = s;
    __syncthreads();
    if (wid == 0) {
        float ss = (lane < WARPS_PER_CTA) ? red[lane] : 0.0f;
#pragma unroll
        for (int o = 4; o; o >>= 1) ss += __shfl_xor_sync(0xffffffffu, ss, o);
        if (lane == 0) red[0] = ss;
    }
    __syncthreads();
    const float inv = rcpf(red[0]);

#pragma unroll
    for (int q = 0; q < 4; ++q) out[tid + 256 * q] = e[q] * inv;
    if (tid == 0) out[CELLS] = ex * inv;
}

extern "C" void kernel_launch(void* const* d_in, const int* in_sizes, int n_in,
                              void* d_out, int out_size)
{
    const float* inp    = (const float*)d_in[0];
    const float* w      = (const float*)d_in[1];
    const float* W_ih   = (const float*)d_in[2];
    const float* W_hh   = (const float*)d_in[3];
    const float* b_ih   = (const float*)d_in[4];
    const float* b_hh   = (const float*)d_in[5];
    const float* conv_w = (const float*)d_in[6];
    const float* conv_b = (const float*)d_in[7];
    float* out = (float*)d_out;

    lstm_fused<<<CTAS, NTHREADS>>>(inp, w, W_ih, W_hh, b_ih, b_hh,
                                   conv_w, conv_b, out);
}